// round 11
// baseline (speedup 1.0000x reference)
#include <cuda_runtime.h>
#include <cstdint>

#define LSEQ 96
#define DM 32
#define NNODES 2000

// 12.3 MB repacked complex frequency weights: [n][j4(12)][lane(32)][4 floats]
// lane = h*8+o ; j = e*6 + m*2 + which (0:W1,1:W2); float slot (j>>2)*128 + lane*4 + (j&3)
__device__ float g_Wc[(size_t)NNODES * 1536];

// ---------------- compile-time trig (constexpr Taylor, exact to ~1e-12) ----------------
__host__ __device__ constexpr double KPI = 3.14159265358979323846;
__host__ __device__ constexpr double tsin_(double x){ double x2=x*x;
  return x*(1 - x2/6*(1 - x2/20*(1 - x2/42*(1 - x2/72*(1 - x2/110*(1 - x2/156*(1 - x2/210)))))));
}
__host__ __device__ constexpr double tcos_(double x){ double x2=x*x;
  return 1 - x2/2*(1 - x2/12*(1 - x2/30*(1 - x2/56*(1 - x2/90*(1 - x2/132*(1 - x2/182))))));
}
__host__ __device__ constexpr double cs96(int k){ k=((k%96)+96)%96; int q=k/24, r=k%24; double x=r*(KPI/48);
  double c=tcos_(x), s=tsin_(x);
  return q==0? c : (q==1? -s : (q==2? -c : s)); }
__host__ __device__ constexpr double sn96(int k){ k=((k%96)+96)%96; int q=k/24, r=k%24; double x=r*(KPI/48);
  double c=tcos_(x), s=tsin_(x);
  return q==0? s : (q==1? c : (q==2? -s : -c)); }

// G_m(t): inverse-mode basis with edge-replicated moving-average detrend folded in.
__host__ __device__ constexpr double Gre_(int f, int t){
  int lo = (t-12 < 0) ? 0 : t-12;
  int hi = (t+12 > 95) ? 95 : t+12;
  double s = 0;
  for (int j = lo; j <= hi; ++j) s += cs96(f*j);
  if (t < 12)  s += (double)(12 - t) * cs96(0);
  if (t > 83)  s += (double)(t - 83) * cs96(f*95);
  return cs96(f*t) - s/25.0;
}
__host__ __device__ constexpr double Gim_(int f, int t){
  int lo = (t-12 < 0) ? 0 : t-12;
  int hi = (t+12 > 95) ? 95 : t+12;
  double s = 0;
  for (int j = lo; j <= hi; ++j) s += sn96(f*j);
  if (t < 12)  s += (double)(12 - t) * sn96(0);
  if (t > 83)  s += (double)(t - 83) * sn96(f*95);
  return sn96(f*t) - s/25.0;
}

// ---------------- W repack kernel (validated, ~6.7us) ----------------
__global__ __launch_bounds__(384)
void repack_kernel(const float* __restrict__ W1, const float* __restrict__ W2)
{
    __shared__ float s[1536];
    const int n = blockIdx.x;
    const int t = threadIdx.x;                  // 0..383

    #pragma unroll
    for (int half = 0; half < 2; ++half) {
        int src = half * 384 + t;               // 0..767, coalesced
        float v1 = W1[(size_t)n * 768 + src];
        float v2 = W2[(size_t)n * 768 + src];
        int h = src / 192, r = src % 192;
        int e = r / 24,   rr = r % 24;
        int o = rr / 3,   m  = rr % 3;
        int lane = h * 8 + o;
        int j1 = e * 6 + m * 2;
        s[(j1 >> 2) * 128 + lane * 4 + (j1 & 3)] = v1;
        int j2 = j1 + 1;
        s[(j2 >> 2) * 128 + lane * 4 + (j2 & 3)] = v2;
    }
    __syncthreads();
    float4 v = *(const float4*)&s[t * 4];
    ((float4*)g_Wc)[(size_t)n * 384 + t] = v;   // coalesced STG.128
}

// ---------------- Phase B: 3-mode DFT, symmetric pairing, immediate trig (GMEM source) ----------------
struct Acc6 { float ar0, ai0, ar1, ai1, ar2, ai2; };

template<int L> __device__ __forceinline__ void bpair(Acc6& a, const float* gx){
  float xl = gx[L*DM];
  float xh = gx[(96-L)*DM];
  float sum = xl + xh, dif = xl - xh;
  constexpr float c0=(float)cs96(1*L), s0=(float)sn96(1*L);
  constexpr float c1=(float)cs96(4*L), s1=(float)sn96(4*L);
  constexpr float c2=(float)cs96(5*L), s2=(float)sn96(5*L);
  a.ar0=fmaf(sum,c0,a.ar0); a.ai0=fmaf(dif,-s0,a.ai0);
  a.ar1=fmaf(sum,c1,a.ar1); a.ai1=fmaf(dif,-s1,a.ai1);
  a.ar2=fmaf(sum,c2,a.ar2); a.ai2=fmaf(dif,-s2,a.ai2);
}
template<int L> __device__ __forceinline__ void bpairs(Acc6& a, const float* gx){
  if constexpr (L <= 47){ bpair<L>(a, gx); bpairs<L+1>(a, gx); }
}

// ---------------- fused inverse-transform + detrend (F+G), GMEM re-read (L1/L2 hits) ----------------
template<int T> __device__ __forceinline__ void fgstep(
    const float* gx, float* op, float ring[26], float& run, float x0, float& x95,
    float zr0, float zi0, float zr1, float zi1, float zr2, float zi2)
{
  float cur = ring[T % 26];
  constexpr float g0r=(float)Gre_(1,T), ng0i=-(float)Gim_(1,T);
  constexpr float g1r=(float)Gre_(4,T), ng1i=-(float)Gim_(4,T);
  constexpr float g2r=(float)Gre_(5,T), ng2i=-(float)Gim_(5,T);
  float v = fmaf(run, -(1.0f/25.0f), cur);     // base = x[t] - trend
  v = fmaf(zr0, g0r, v);  v = fmaf(zi0, ng0i, v);
  v = fmaf(zr1, g1r, v);  v = fmaf(zi1, ng1i, v);
  v = fmaf(zr2, g2r, v);  v = fmaf(zi2, ng2i, v);
  op[T*DM] = v;                                // coalesced STG, fire-and-forget
  float subv = (T-12 >= 0) ? ring[(T+14) % 26] : x0;
  float addv;
  if constexpr (T+13 <= 95) addv = gx[(T+13)*DM]; else addv = x95;
  if constexpr (T+13 == 95) x95 = addv;
  ring[(T+13) % 26] = addv;
  run += addv - subv;
}
template<int T> __device__ __forceinline__ void fgloop(
    const float* gx, float* op, float ring[26], float& run, float x0, float& x95,
    float zr0, float zi0, float zr1, float zi1, float zr2, float zi2)
{
  if constexpr (T < LSEQ){
    fgstep<T>(gx, op, ring, run, x0, x95, zr0, zi0, zr1, zi1, zr2, zi2);
    fgloop<T+1>(gx, op, ring, run, x0, x95, zr0, zi0, zr1, zi1, zr2, zi2);
  }
}

// One warp per (b,n) tile of [96 x 32], lane == channel d. 2 warps/block, grid 8000.
// No x smem tile; 2KB smem/block; regs capped ~85 by launch_bounds -> 24 warps/SM.
__global__ __launch_bounds__(64, 12)
void feldm_kernel(const float* __restrict__ x,
                  const float* __restrict__ Wq,
                  const float* __restrict__ Wo,
                  float* __restrict__ out)
{
    __shared__ float4 scr4[2][DM];     // exchange: modes 0,1
    __shared__ float2 scr2[2][DM];     // exchange: mode 2

    const int tid  = threadIdx.x;
    const int warp = tid >> 5;
    const int lane = tid & 31;

    const int unit = blockIdx.x * 2 + warp;     // b*2000 + n
    const int n    = unit % 2000;
    const float* __restrict__ gx = x   + (size_t)unit * (LSEQ * DM) + lane;
    float* __restrict__       op = out + (size_t)unit * (LSEQ * DM) + lane;

    // ---- Phase B: 3-mode DFT straight from GMEM (coalesced, high-MLP unrolled) ----
    float xv0 = gx[0], xv48 = gx[48*DM];
    Acc6 a;
    a.ar0 = xv0 - xv48; a.ai0 = 0.f;    // f=1: cos(pi)  = -1 at l=48
    a.ar1 = xv0 + xv48; a.ai1 = 0.f;    // f=4: cos(4pi) = +1
    a.ar2 = xv0 - xv48; a.ai2 = 0.f;    // f=5: cos(5pi) = -1
    bpairs<1>(a, gx);
    scr4[warp][lane] = make_float4(a.ar0, a.ai0, a.ar1, a.ai1);
    scr2[warp][lane] = make_float2(a.ar2, a.ai2);
    __syncwarp();

    // ---- Phase C: Xq[c,m] = sum_d Wq[c,d] * Xx[d,m]  (bq feeds only mode 0 -> drops) ----
    float wrow[32];
    #pragma unroll
    for (int j = 0; j < 8; ++j) {
        float4 v = *(const float4*)&Wq[lane * 32 + 4 * j];
        wrow[4*j] = v.x; wrow[4*j+1] = v.y; wrow[4*j+2] = v.z; wrow[4*j+3] = v.w;
    }
    float qr0=0.f,qi0=0.f,qr1=0.f,qi1=0.f,qr2=0.f,qi2=0.f;
    #pragma unroll
    for (int d = 0; d < 32; ++d) {
        float4 t0 = scr4[warp][d];
        float2 t1 = scr2[warp][d];
        float wv = wrow[d];
        qr0 = fmaf(wv, t0.x, qr0); qi0 = fmaf(wv, t0.y, qi0);
        qr1 = fmaf(wv, t0.z, qr1); qi1 = fmaf(wv, t0.w, qi1);
        qr2 = fmaf(wv, t1.x, qr2); qi2 = fmaf(wv, t1.y, qi2);
    }
    __syncwarp();
    scr4[warp][lane] = make_float4(qr0, qi0, qr1, qi1);
    scr2[warp][lane] = make_float2(qr2, qi2);
    __syncwarp();

    // ---- Phase D: per-head complex 8x8 mix; weights streamed here (coalesced LDG.128) ----
    const int h = lane >> 3;
    float or0=0.f,oi0=0.f,or1=0.f,oi1=0.f,or2=0.f,oi2=0.f;
    {
        const float4* wc = (const float4*)g_Wc + (size_t)n * 384 + lane;
        #pragma unroll
        for (int e2 = 0; e2 < 4; ++e2) {            // 2 e-values per trip, 3 float4 each
            float4 wa = wc[(e2*3 + 0) * 32];
            float4 wb = wc[(e2*3 + 1) * 32];
            float4 wd = wc[(e2*3 + 2) * 32];
            {
                int e = e2 * 2;
                float4 t0 = scr4[warp][h * 8 + e];
                float2 t1 = scr2[warp][h * 8 + e];
                or0 += t0.x*wa.x - t0.y*wa.y;  oi0 += t0.x*wa.y + t0.y*wa.x;
                or1 += t0.z*wa.z - t0.w*wa.w;  oi1 += t0.z*wa.w + t0.w*wa.z;
                or2 += t1.x*wb.x - t1.y*wb.y;  oi2 += t1.x*wb.y + t1.y*wb.x;
            }
            {
                int e = e2 * 2 + 1;
                float4 t0 = scr4[warp][h * 8 + e];
                float2 t1 = scr2[warp][h * 8 + e];
                or0 += t0.x*wb.z - t0.y*wb.w;  oi0 += t0.x*wb.w + t0.y*wb.z;
                or1 += t0.z*wd.x - t0.w*wd.y;  oi1 += t0.z*wd.y + t0.w*wd.x;
                or2 += t1.x*wd.z - t1.y*wd.w;  oi2 += t1.x*wd.w + t1.y*wd.z;
            }
        }
    }
    __syncwarp();
    scr4[warp][lane] = make_float4(or0, oi0, or1, oi1);
    scr2[warp][lane] = make_float2(or2, oi2);
    __syncwarp();

    // ---- Phase E: Z[dout,m] = (2/96) * sum_c O[c,m] * Wo[dout,c] ----
    #pragma unroll
    for (int j = 0; j < 8; ++j) {
        float4 v = *(const float4*)&Wo[lane * 32 + 4 * j];
        wrow[4*j] = v.x; wrow[4*j+1] = v.y; wrow[4*j+2] = v.z; wrow[4*j+3] = v.w;
    }
    float zr0=0.f,zi0=0.f,zr1=0.f,zi1=0.f,zr2=0.f,zi2=0.f;
    #pragma unroll
    for (int c = 0; c < 32; ++c) {
        float4 t0 = scr4[warp][c];
        float2 t1 = scr2[warp][c];
        float wv = wrow[c];
        zr0 = fmaf(wv, t0.x, zr0); zi0 = fmaf(wv, t0.y, zi0);
        zr1 = fmaf(wv, t0.z, zr1); zi1 = fmaf(wv, t0.w, zi1);
        zr2 = fmaf(wv, t1.x, zr2); zi2 = fmaf(wv, t1.y, zi2);
    }
    const float inv = 2.0f / 96.0f;
    zr0 *= inv; zi0 *= inv; zr1 *= inv; zi1 *= inv; zr2 *= inv; zi2 *= inv;
    // bo cancels exactly in (xr - movavg(xr)): every window averages 25 values.

    // ---- Phases F+G fused: out[t] = (x[t] - run/25) + Re(sum_m Z_m G_m(t)) ----
    float ring[26];
    #pragma unroll
    for (int j = 0; j < 13; ++j) ring[j] = gx[j*DM];   // L1/L2 hits (just-read lines)
    float x0 = ring[0], x95 = 0.f;
    float run = 12.0f * x0;
    #pragma unroll
    for (int j = 0; j < 13; ++j) run += ring[j];

    fgloop<0>(gx, op, ring, run, x0, x95, zr0, zi0, zr1, zi1, zr2, zi2);
}

extern "C" void kernel_launch(void* const* d_in, const int* in_sizes, int n_in,
                              void* d_out, int out_size) {
    // metadata order: x, Wq, bq, Wk, bk, Wv, bv, Wo, bo, W1, W2
    const float* x  = (const float*)d_in[0];
    const float* Wq = (const float*)d_in[1];
    const float* Wo = (const float*)d_in[7];
    const float* W1 = (const float*)d_in[9];
    const float* W2 = (const float*)d_in[10];
    repack_kernel<<<NNODES, 384>>>(W1, W2);
    feldm_kernel<<<8000, 64>>>(x, Wq, Wo, (float*)d_out);
}

// round 13
// speedup vs baseline: 2.0922x; 2.0922x over previous
#include <cuda_runtime.h>
#include <cstdint>

#define LSEQ 96
#define DM 32
#define NNODES 2000

// 12.3 MB repacked complex frequency weights: [n][j4(12)][lane(32)][4 floats]
// lane = h*8+o ; j = e*6 + m*2 + which (0:W1,1:W2); float slot (j>>2)*128 + lane*4 + (j&3)
__device__ float g_Wc[(size_t)NNODES * 1536];

// ---------------- compile-time trig (constexpr Taylor, exact to ~1e-12) ----------------
__host__ __device__ constexpr double KPI = 3.14159265358979323846;
__host__ __device__ constexpr double tsin_(double x){ double x2=x*x;
  return x*(1 - x2/6*(1 - x2/20*(1 - x2/42*(1 - x2/72*(1 - x2/110*(1 - x2/156*(1 - x2/210)))))));
}
__host__ __device__ constexpr double tcos_(double x){ double x2=x*x;
  return 1 - x2/2*(1 - x2/12*(1 - x2/30*(1 - x2/56*(1 - x2/90*(1 - x2/132*(1 - x2/182))))));
}
__host__ __device__ constexpr double cs96(int k){ k=((k%96)+96)%96; int q=k/24, r=k%24; double x=r*(KPI/48);
  double c=tcos_(x), s=tsin_(x);
  return q==0? c : (q==1? -s : (q==2? -c : s)); }
__host__ __device__ constexpr double sn96(int k){ k=((k%96)+96)%96; int q=k/24, r=k%24; double x=r*(KPI/48);
  double c=tcos_(x), s=tsin_(x);
  return q==0? s : (q==1? c : (q==2? -s : -c)); }

// G_m(t): inverse-mode basis with edge-replicated moving-average detrend folded in.
__host__ __device__ constexpr double Gre_(int f, int t){
  int lo = (t-12 < 0) ? 0 : t-12;
  int hi = (t+12 > 95) ? 95 : t+12;
  double s = 0;
  for (int j = lo; j <= hi; ++j) s += cs96(f*j);
  if (t < 12)  s += (double)(12 - t) * cs96(0);
  if (t > 83)  s += (double)(t - 83) * cs96(f*95);
  return cs96(f*t) - s/25.0;
}
__host__ __device__ constexpr double Gim_(int f, int t){
  int lo = (t-12 < 0) ? 0 : t-12;
  int hi = (t+12 > 95) ? 95 : t+12;
  double s = 0;
  for (int j = lo; j <= hi; ++j) s += sn96(f*j);
  if (t < 12)  s += (double)(12 - t) * sn96(0);
  if (t > 83)  s += (double)(t - 83) * sn96(f*95);
  return sn96(f*t) - s/25.0;
}

// ---------------- W repack kernel (validated) ----------------
__global__ __launch_bounds__(384)
void repack_kernel(const float* __restrict__ W1, const float* __restrict__ W2)
{
    __shared__ float s[1536];
    const int n = blockIdx.x;
    const int t = threadIdx.x;                  // 0..383

    #pragma unroll
    for (int half = 0; half < 2; ++half) {
        int src = half * 384 + t;               // 0..767, coalesced
        float v1 = W1[(size_t)n * 768 + src];
        float v2 = W2[(size_t)n * 768 + src];
        int h = src / 192, r = src % 192;
        int e = r / 24,   rr = r % 24;
        int o = rr / 3,   m  = rr % 3;
        int lane = h * 8 + o;
        int j1 = e * 6 + m * 2;
        s[(j1 >> 2) * 128 + lane * 4 + (j1 & 3)] = v1;
        int j2 = j1 + 1;
        s[(j2 >> 2) * 128 + lane * 4 + (j2 & 3)] = v2;
    }
    __syncthreads();
    float4 v = *(const float4*)&s[t * 4];
    ((float4*)g_Wc)[(size_t)n * 384 + t] = v;   // coalesced STG.128
}

// ---------------- load x column into registers (compile-time indexed) ----------------
template<int L> __device__ __forceinline__ void xload(float (&xr)[LSEQ], const float* gx){
  if constexpr (L < LSEQ){
    xr[L] = gx[L*DM];                 // coalesced LDG.32, batched by ptxas
    xload<L+1>(xr, gx);
  }
}

// ---------------- Phase B: 3-mode DFT, symmetric pairing, immediate trig (register source) ----------------
struct Acc6 { float ar0, ai0, ar1, ai1, ar2, ai2; };

template<int L> __device__ __forceinline__ void bpairs(Acc6& a, const float (&xr)[LSEQ]){
  if constexpr (L <= 47){
    float sum = xr[L] + xr[96-L], dif = xr[L] - xr[96-L];
    constexpr float c0=(float)cs96(1*L), s0=(float)sn96(1*L);
    constexpr float c1=(float)cs96(4*L), s1=(float)sn96(4*L);
    constexpr float c2=(float)cs96(5*L), s2=(float)sn96(5*L);
    a.ar0=fmaf(sum,c0,a.ar0); a.ai0=fmaf(dif,-s0,a.ai0);
    a.ar1=fmaf(sum,c1,a.ar1); a.ai1=fmaf(dif,-s1,a.ai1);
    a.ar2=fmaf(sum,c2,a.ar2); a.ai2=fmaf(dif,-s2,a.ai2);
    bpairs<L+1>(a, xr);
  }
}

// ---------------- fused inverse-transform + detrend (F+G), pure register source ----------------
template<int T> __device__ __forceinline__ void fgloop(
    const float (&xr)[LSEQ], float* op, float& run,
    float zr0, float zi0, float zr1, float zi1, float zr2, float zi2)
{
  if constexpr (T < LSEQ){
    constexpr float g0r=(float)Gre_(1,T), ng0i=-(float)Gim_(1,T);
    constexpr float g1r=(float)Gre_(4,T), ng1i=-(float)Gim_(4,T);
    constexpr float g2r=(float)Gre_(5,T), ng2i=-(float)Gim_(5,T);
    float v = fmaf(run, -(1.0f/25.0f), xr[T]);   // base = x[t] - trend
    v = fmaf(zr0, g0r, v);  v = fmaf(zi0, ng0i, v);
    v = fmaf(zr1, g1r, v);  v = fmaf(zi1, ng1i, v);
    v = fmaf(zr2, g2r, v);  v = fmaf(zi2, ng2i, v);
    op[T*DM] = v;                                // coalesced STG, fire-and-forget
    constexpr int ia = (T+13 <= 95) ? T+13 : 95;
    constexpr int is = (T-12 >= 0) ? T-12 : 0;
    run += xr[ia] - xr[is];
    fgloop<T+1>(xr, op, run, zr0, zi0, zr1, zi1, zr2, zi2);
  }
}

// One warp per (b,n) tile of [96 x 32], lane == channel d. 2 warps/block, grid 8000.
// x column lives in registers; smem only for the 1.5KB mode exchange.
__global__ __launch_bounds__(64, 8)
void feldm_kernel(const float* __restrict__ x,
                  const float* __restrict__ Wq,
                  const float* __restrict__ Wo,
                  float* __restrict__ out)
{
    __shared__ float4 scr4[2][DM];     // exchange: modes 0,1
    __shared__ float2 scr2[2][DM];     // exchange: mode 2

    const int tid  = threadIdx.x;
    const int warp = tid >> 5;
    const int lane = tid & 31;

    const int unit = blockIdx.x * 2 + warp;     // b*2000 + n
    const int n    = unit % 2000;
    const float* __restrict__ gx = x   + (size_t)unit * (LSEQ * DM) + lane;
    float* __restrict__       op = out + (size_t)unit * (LSEQ * DM) + lane;

    // ---- load the whole x column into registers (96 coalesced LDG, deep MLP) ----
    float xr[LSEQ];
    xload<0>(xr, gx);

    // ---- Phase B: 3-mode DFT (l=0 & l=48 special; pairs 1..47) ----
    Acc6 a;
    a.ar0 = xr[0] - xr[48]; a.ai0 = 0.f;    // f=1: cos(pi)  = -1
    a.ar1 = xr[0] + xr[48]; a.ai1 = 0.f;    // f=4: cos(4pi) = +1
    a.ar2 = xr[0] - xr[48]; a.ai2 = 0.f;    // f=5: cos(5pi) = -1
    bpairs<1>(a, xr);
    scr4[warp][lane] = make_float4(a.ar0, a.ai0, a.ar1, a.ai1);
    scr2[warp][lane] = make_float2(a.ar2, a.ai2);
    __syncwarp();

    // ---- Phase C: Xq[c,m] = sum_d Wq[c,d] * Xx[d,m]  (bq feeds only mode 0 -> drops) ----
    float qr0=0.f,qi0=0.f,qr1=0.f,qi1=0.f,qr2=0.f,qi2=0.f;
    {
        const float4* wq = (const float4*)(Wq + lane * 32);
        #pragma unroll
        for (int j = 0; j < 8; ++j) {
            float4 wv = wq[j];                   // streamed, small live window
            #pragma unroll
            for (int k = 0; k < 4; ++k) {
                int d = 4*j + k;
                float wk = (k==0)? wv.x : (k==1)? wv.y : (k==2)? wv.z : wv.w;
                float4 t0 = scr4[warp][d];       // broadcast LDS
                float2 t1 = scr2[warp][d];
                qr0 = fmaf(wk, t0.x, qr0); qi0 = fmaf(wk, t0.y, qi0);
                qr1 = fmaf(wk, t0.z, qr1); qi1 = fmaf(wk, t0.w, qi1);
                qr2 = fmaf(wk, t1.x, qr2); qi2 = fmaf(wk, t1.y, qi2);
            }
        }
    }
    __syncwarp();
    scr4[warp][lane] = make_float4(qr0, qi0, qr1, qi1);
    scr2[warp][lane] = make_float2(qr2, qi2);
    __syncwarp();

    // ---- Phase D: per-head complex 8x8 mix; weights streamed (coalesced LDG.128) ----
    const int h = lane >> 3;
    float or0=0.f,oi0=0.f,or1=0.f,oi1=0.f,or2=0.f,oi2=0.f;
    {
        const float4* wc = (const float4*)g_Wc + (size_t)n * 384 + lane;
        #pragma unroll
        for (int e2 = 0; e2 < 4; ++e2) {            // 2 e-values per trip, 3 float4 each
            float4 wa = wc[(e2*3 + 0) * 32];
            float4 wb = wc[(e2*3 + 1) * 32];
            float4 wd = wc[(e2*3 + 2) * 32];
            {
                int e = e2 * 2;
                float4 t0 = scr4[warp][h * 8 + e];
                float2 t1 = scr2[warp][h * 8 + e];
                or0 += t0.x*wa.x - t0.y*wa.y;  oi0 += t0.x*wa.y + t0.y*wa.x;
                or1 += t0.z*wa.z - t0.w*wa.w;  oi1 += t0.z*wa.w + t0.w*wa.z;
                or2 += t1.x*wb.x - t1.y*wb.y;  oi2 += t1.x*wb.y + t1.y*wb.x;
            }
            {
                int e = e2 * 2 + 1;
                float4 t0 = scr4[warp][h * 8 + e];
                float2 t1 = scr2[warp][h * 8 + e];
                or0 += t0.x*wb.z - t0.y*wb.w;  oi0 += t0.x*wb.w + t0.y*wb.z;
                or1 += t0.z*wd.x - t0.w*wd.y;  oi1 += t0.z*wd.y + t0.w*wd.x;
                or2 += t1.x*wd.z - t1.y*wd.w;  oi2 += t1.x*wd.w + t1.y*wd.z;
            }
        }
    }
    __syncwarp();
    scr4[warp][lane] = make_float4(or0, oi0, or1, oi1);
    scr2[warp][lane] = make_float2(or2, oi2);
    __syncwarp();

    // ---- Phase E: Z[dout,m] = (2/96) * sum_c O[c,m] * Wo[dout,c] ----
    float zr0=0.f,zi0=0.f,zr1=0.f,zi1=0.f,zr2=0.f,zi2=0.f;
    {
        const float4* wo = (const float4*)(Wo + lane * 32);
        #pragma unroll
        for (int j = 0; j < 8; ++j) {
            float4 wv = wo[j];
            #pragma unroll
            for (int k = 0; k < 4; ++k) {
                int c = 4*j + k;
                float wk = (k==0)? wv.x : (k==1)? wv.y : (k==2)? wv.z : wv.w;
                float4 t0 = scr4[warp][c];
                float2 t1 = scr2[warp][c];
                zr0 = fmaf(wk, t0.x, zr0); zi0 = fmaf(wk, t0.y, zi0);
                zr1 = fmaf(wk, t0.z, zr1); zi1 = fmaf(wk, t0.w, zi1);
                zr2 = fmaf(wk, t1.x, zr2); zi2 = fmaf(wk, t1.y, zi2);
            }
        }
    }
    const float inv = 2.0f / 96.0f;
    zr0 *= inv; zi0 *= inv; zr1 *= inv; zi1 *= inv; zr2 *= inv; zi2 *= inv;
    // bo cancels exactly in (xr - movavg(xr)): every window averages 25 values.

    // ---- Phases F+G fused (pure registers): out[t] = (x[t] - run/25) + Re(sum_m Z_m G_m(t)) ----
    float run = 12.0f * xr[0];
    #pragma unroll
    for (int j = 0; j < 13; ++j) run += xr[j];

    fgloop<0>(xr, op, run, zr0, zi0, zr1, zi1, zr2, zi2);
}

extern "C" void kernel_launch(void* const* d_in, const int* in_sizes, int n_in,
                              void* d_out, int out_size) {
    // metadata order: x, Wq, bq, Wk, bk, Wv, bv, Wo, bo, W1, W2
    const float* x  = (const float*)d_in[0];
    const float* Wq = (const float*)d_in[1];
    const float* Wo = (const float*)d_in[7];
    const float* W1 = (const float*)d_in[9];
    const float* W2 = (const float*)d_in[10];
    repack_kernel<<<NNODES, 384>>>(W1, W2);
    feldm_kernel<<<8000, 64>>>(x, Wq, Wo, (float*)d_out);
}